// round 5
// baseline (speedup 1.0000x reference)
#include <cuda_runtime.h>
#include <math.h>
#include <stdint.h>

// ---------------- problem constants ----------------
#define NLITS 4000
#define NCLS  8000
#define E     128
#define H1    400
#define H2    200
#define H2P   208          // H2 padded to multiple of 16
#define NG    512          // 4*E LSTM gates
#define TSTEPS 30
#define LIT_STRIDE 512
#define CLS_STRIDE 256
#define VOTE_BLOCKS ((NLITS + 7) / 8)
#define BK 16
#define SP 20              // smem row stride in floats (16 + 4 pad)

// ---------------- device scratch (static, BSS zero-init, allocation-free) ----------------
__device__ float g_Lh[NLITS * E], g_Lc[NLITS * E];
__device__ float g_Ch[NCLS * E],  g_Cc[NCLS * E];
__device__ float g_b1L[NLITS * H1], g_b1C[NCLS * H1];
__device__ float g_b2L[NLITS * H2P], g_b2C[NCLS * H2P];   // pad cols stay 0 (never written)
__device__ float g_mlpL[NLITS * E],  g_mlpC[NCLS * E];
__device__ float g_msgL[NLITS * E],  g_msgC[NCLS * E];
__device__ float g_gatesC[NCLS * NG], g_gatesL[NLITS * NG];
__device__ float g_LC3p[E * H2P], g_CL3p[E * H2P];        // K-padded copies of W3s
__device__ int   g_lit_idx[(size_t)NLITS * LIT_STRIDE];
__device__ int   g_lit_len[NLITS];
__device__ int   g_cls_idx[(size_t)NCLS * CLS_STRIDE];
__device__ int   g_cls_len[NCLS];
__device__ float g_partials[VOTE_BLOCKS];

// ---------------- adjacency builders ----------------
__global__ void build_lit_kernel(const float* __restrict__ M) {
    int l = blockIdx.x * (blockDim.x >> 5) + (threadIdx.x >> 5);
    int lane = threadIdx.x & 31;
    if (l >= NLITS) return;
    const float* row = M + (size_t)l * NCLS;
    int cnt = 0;
    for (int c0 = 0; c0 < NCLS; c0 += 32) {
        float v = row[c0 + lane];
        unsigned mask = __ballot_sync(0xffffffffu, v != 0.0f);
        if (v != 0.0f) {
            int pos = cnt + __popc(mask & ((1u << lane) - 1u));
            if (pos < LIT_STRIDE) g_lit_idx[(size_t)l * LIT_STRIDE + pos] = c0 + lane;
        }
        cnt += __popc(mask);
    }
    if (lane == 0) g_lit_len[l] = cnt < LIT_STRIDE ? cnt : LIT_STRIDE;
}

__global__ void build_cls_kernel(const float* __restrict__ M) {
    int c = blockIdx.x * (blockDim.x >> 5) + (threadIdx.x >> 5);
    int lane = threadIdx.x & 31;
    if (c >= NCLS) return;
    int cnt = 0;
    for (int l0 = 0; l0 < NLITS; l0 += 32) {
        float v = M[(size_t)(l0 + lane) * NCLS + c];
        unsigned mask = __ballot_sync(0xffffffffu, v != 0.0f);
        if (v != 0.0f) {
            int pos = cnt + __popc(mask & ((1u << lane) - 1u));
            if (pos < CLS_STRIDE) g_cls_idx[(size_t)c * CLS_STRIDE + pos] = l0 + lane;
        }
        cnt += __popc(mask);
    }
    if (lane == 0) g_cls_len[c] = cnt < CLS_STRIDE ? cnt : CLS_STRIDE;
}

// ---------------- W3 K-padding (200 -> 208, pad zeros) ----------------
__global__ void pad_w3_kernel(const float* __restrict__ in, float* __restrict__ out) {
    int i = blockIdx.x * blockDim.x + threadIdx.x;
    if (i >= E * H2P) return;
    int r = i / H2P, k = i - r * H2P;
    out[i] = (k < H2) ? in[(size_t)r * H2 + k] : 0.0f;
}

// ---------------- state init ----------------
__global__ void init_states_kernel(const float* __restrict__ L_init,
                                   const float* __restrict__ C_init) {
    int i = blockIdx.x * blockDim.x + threadIdx.x;
    const int totL = NLITS * E;
    if (i < totL) {
        g_Lh[i] = L_init[i & (E - 1)]; g_Lc[i] = 0.0f;
    } else if (i < totL + NCLS * E) {
        int j = i - totL;
        g_Ch[j] = C_init[j & (E - 1)]; g_Cc[j] = 0.0f;
    }
}

// ---------------- 3xTF32 tensor-core GEMM ----------------
// C = act( sum_seg A[seg] @ B[seg]^T + bias );  A:[M,K] fp32 row-major,
// B:[N,K] fp32 row-major, fp32 out. Split to tf32 hi/lo in registers.
struct GP {
    const float* A[2];
    const float* B[2];
    const float* bias;
    float* out;
    int M;
    int nseg;
};

__device__ __forceinline__ void tf32_split(float v, uint32_t& hi, uint32_t& lo) {
    uint32_t h;
    asm("cvt.rna.tf32.f32 %0, %1;" : "=r"(h) : "f"(v));
    float l = v - __uint_as_float(h);
    uint32_t lw;
    asm("cvt.rna.tf32.f32 %0, %1;" : "=r"(lw) : "f"(l));
    hi = h; lo = lw;
}

#define MMA_TF32(C, A, B)                                              \
    asm volatile(                                                      \
        "mma.sync.aligned.m16n8k8.row.col.f32.tf32.tf32.f32 "          \
        "{%0,%1,%2,%3}, {%4,%5,%6,%7}, {%8,%9}, {%0,%1,%2,%3};"        \
        : "+f"((C)[0]), "+f"((C)[1]), "+f"((C)[2]), "+f"((C)[3])       \
        : "r"((A)[0]), "r"((A)[1]), "r"((A)[2]), "r"((A)[3]),          \
          "r"((B)[0]), "r"((B)[1]))

template <bool RELU>
__global__ void __launch_bounds__(256) gemm_tf32x3_kernel(GP p0, GP p1, int N, int K, int opitch)
{
    const GP p = (blockIdx.z == 0) ? p0 : p1;
    const int m0 = blockIdx.y * 128;
    if (m0 >= p.M) return;
    const int n0 = blockIdx.x * 128;

    __shared__ float As[2][128][SP];
    __shared__ float Bs[2][128][SP];

    const int tid = threadIdx.x;
    const int lane = tid & 31;
    const int wid = tid >> 5;
    const int wm0 = (wid & 3) * 32;   // 4 warps over M
    const int wn0 = (wid >> 2) * 64;  // 2 warps over N
    const int g = lane >> 2;          // group id (row within 8 / col within 8)
    const int q = lane & 3;           // thread in group

    const int ntiles = K / BK;
    const int total = ntiles * p.nseg;

    float c[2][8][4];
#pragma unroll
    for (int a = 0; a < 2; a++)
#pragma unroll
        for (int b = 0; b < 8; b++)
#pragma unroll
            for (int d = 0; d < 4; d++) c[a][b][d] = 0.0f;

    float4 va[2], vb[2];

    auto load_g = [&](int ti) {
        int seg = ti / ntiles;
        int k0 = (ti - seg * ntiles) * BK;
        const float* Ap = p.A[seg];
        const float* Bp = p.B[seg];
#pragma unroll
        for (int i = 0; i < 2; i++) {
            int idx = tid + i * 256;
            int row = idx >> 2;
            int qq = idx & 3;
            float4 v = make_float4(0.f, 0.f, 0.f, 0.f);
            int gr = m0 + row;
            if (gr < p.M) v = *(const float4*)(Ap + (size_t)gr * K + k0 + qq * 4);
            va[i] = v;
            float4 w = make_float4(0.f, 0.f, 0.f, 0.f);
            int gn = n0 + row;
            if (gn < N) w = *(const float4*)(Bp + (size_t)gn * K + k0 + qq * 4);
            vb[i] = w;
        }
    };
    auto store_s = [&](int buf) {
#pragma unroll
        for (int i = 0; i < 2; i++) {
            int idx = tid + i * 256;
            int row = idx >> 2;
            int qq = idx & 3;
            *(float4*)&As[buf][row][qq * 4] = va[i];
            *(float4*)&Bs[buf][row][qq * 4] = vb[i];
        }
    };

    load_g(0);
    store_s(0);
    __syncthreads();

    int buf = 0;
    for (int t = 0; t < total; t++) {
        if (t + 1 < total) load_g(t + 1);

#pragma unroll
        for (int kk = 0; kk < 2; kk++) {
            const int cb = kk * 8;
            uint32_t ah[2][4], al[2][4];
#pragma unroll
            for (int mt = 0; mt < 2; mt++) {
                int r0 = wm0 + mt * 16 + g;
                tf32_split(As[buf][r0][cb + q],         ah[mt][0], al[mt][0]);
                tf32_split(As[buf][r0 + 8][cb + q],     ah[mt][1], al[mt][1]);
                tf32_split(As[buf][r0][cb + q + 4],     ah[mt][2], al[mt][2]);
                tf32_split(As[buf][r0 + 8][cb + q + 4], ah[mt][3], al[mt][3]);
            }
#pragma unroll
            for (int ng = 0; ng < 8; ng++) {
                uint32_t bh[2], bl[2];
                int brow = wn0 + ng * 8 + g;
                tf32_split(Bs[buf][brow][cb + q],     bh[0], bl[0]);
                tf32_split(Bs[buf][brow][cb + q + 4], bh[1], bl[1]);
#pragma unroll
                for (int mt = 0; mt < 2; mt++) {
                    MMA_TF32(c[mt][ng], ah[mt], bh);   // hi * hi
                    MMA_TF32(c[mt][ng], ah[mt], bl);   // hi * lo
                    MMA_TF32(c[mt][ng], al[mt], bh);   // lo * hi
                }
            }
        }

        if (t + 1 < total) store_s(buf ^ 1);
        __syncthreads();
        buf ^= 1;
    }

    // epilogue: + bias, optional relu, guarded fp32 store
#pragma unroll
    for (int mt = 0; mt < 2; mt++) {
#pragma unroll
        for (int ng = 0; ng < 8; ng++) {
            int col = n0 + wn0 + ng * 8 + q * 2;
            if (col >= N) continue;
            float b0 = p.bias[col], b1 = p.bias[col + 1];
#pragma unroll
            for (int half = 0; half < 2; half++) {
                int row = m0 + wm0 + mt * 16 + g + half * 8;
                if (row >= p.M) continue;
                float v0 = c[mt][ng][half * 2 + 0] + b0;
                float v1 = c[mt][ng][half * 2 + 1] + b1;
                if (RELU) { v0 = fmaxf(v0, 0.0f); v1 = fmaxf(v1, 0.0f); }
                *(float2*)(p.out + (size_t)row * opitch + col) = make_float2(v0, v1);
            }
        }
    }
}

template <bool RELU>
static inline void launch_gemm(GP p0, GP p1, int nz, int N, int K, int opitch) {
    int mmax = p0.M;
    if (nz > 1 && p1.M > mmax) mmax = p1.M;
    dim3 grid((N + 127) / 128, (mmax + 127) / 128, nz);
    gemm_tf32x3_kernel<RELU><<<grid, 256>>>(p0, p1, N, K, opitch);
}

// ---------------- combined SpMM gather (both directions in one launch) ----------------
// rows [0, NCLS): msgC[r] = sum over cls list of mlpL rows
// rows [NCLS, NCLS+NLITS): msgL[r'] = sum over lit list of mlpC rows
__global__ void spmm_both_kernel() {
    int r = (blockIdx.x * blockDim.x + threadIdx.x) >> 5;
    if (r >= NCLS + NLITS) return;
    int lane = threadIdx.x & 31;

    const int* lst; int n; const float* in; float* outp;
    if (r < NCLS) {
        lst = g_cls_idx + (size_t)r * CLS_STRIDE; n = g_cls_len[r];
        in = g_mlpL; outp = g_msgC + (size_t)r * E;
    } else {
        int rr = r - NCLS;
        lst = g_lit_idx + (size_t)rr * LIT_STRIDE; n = g_lit_len[rr];
        in = g_mlpC; outp = g_msgL + (size_t)rr * E;
    }

    float4 acc = make_float4(0.f, 0.f, 0.f, 0.f);
    int j = 0;
    for (; j + 4 <= n; j += 4) {
        int i0 = lst[j], i1 = lst[j + 1], i2 = lst[j + 2], i3 = lst[j + 3];
        float4 v0 = ((const float4*)(in + (size_t)i0 * E))[lane];
        float4 v1 = ((const float4*)(in + (size_t)i1 * E))[lane];
        float4 v2 = ((const float4*)(in + (size_t)i2 * E))[lane];
        float4 v3 = ((const float4*)(in + (size_t)i3 * E))[lane];
        acc.x += v0.x + v1.x + v2.x + v3.x;
        acc.y += v0.y + v1.y + v2.y + v3.y;
        acc.z += v0.z + v1.z + v2.z + v3.z;
        acc.w += v0.w + v1.w + v2.w + v3.w;
    }
    for (; j < n; j++) {
        float4 v = ((const float4*)(in + (size_t)lst[j] * E))[lane];
        acc.x += v.x; acc.y += v.y; acc.z += v.z; acc.w += v.w;
    }
    ((float4*)outp)[lane] = acc;
}

// ---------------- LSTM pointwise (both node types) ----------------
__device__ __forceinline__ float sigmoidf_(float x) { return 1.0f / (1.0f + expf(-x)); }

__global__ void lstm_pointwise_both() {
    int i = blockIdx.x * blockDim.x + threadIdx.x;
    const int totalC = NCLS * E;
    if (i >= totalC + NLITS * E) return;

    const float* gmat; float* cvec; float* hvec; int e;
    if (i < totalC) { gmat = g_gatesC; cvec = g_Cc; hvec = g_Ch; e = i; }
    else            { gmat = g_gatesL; cvec = g_Lc; hvec = g_Lh; e = i - totalC; }

    int row = e >> 7;
    int col = e & (E - 1);
    const float* gr = gmat + (size_t)row * NG;
    float ig = sigmoidf_(gr[col]);
    float fg = sigmoidf_(gr[E + col]);
    float gg = tanhf(gr[2 * E + col]);
    float og = sigmoidf_(gr[3 * E + col]);
    float c2 = fg * cvec[e] + ig * gg;
    cvec[e] = c2;
    hvec[e] = og * tanhf(c2);
}

// ---------------- vote + reduction ----------------
__global__ void vote_partial_kernel(const float* __restrict__ X2,
                                    const float* __restrict__ W3,
                                    const float* __restrict__ b3,
                                    float* __restrict__ partials) {
    int warp = (blockIdx.x * blockDim.x + threadIdx.x) >> 5;
    int lane = threadIdx.x & 31;
    float vote = 0.0f;
    if (warp < NLITS) {
        const float* x = X2 + (size_t)warp * H2P;
        float s = 0.0f;
        for (int jj = lane; jj < H2; jj += 32) s += x[jj] * W3[jj];
#pragma unroll
        for (int o = 16; o; o >>= 1) s += __shfl_down_sync(0xffffffffu, s, o);
        if (lane == 0) vote = sigmoidf_(s + b3[0]);
    }
    __shared__ float sm[8];
    if (lane == 0) sm[threadIdx.x >> 5] = vote;
    __syncthreads();
    if (threadIdx.x == 0) {
        float t = 0.0f;
        for (int w = 0; w < 8; w++) t += sm[w];
        partials[blockIdx.x] = t;
    }
}

__global__ void finalize_kernel(const float* __restrict__ partials, int n,
                                float* __restrict__ out) {
    __shared__ float sm[512];
    float s = 0.0f;
    for (int i = threadIdx.x; i < n; i += blockDim.x) s += partials[i];
    sm[threadIdx.x] = s;
    __syncthreads();
    for (int o = 256; o; o >>= 1) {
        if (threadIdx.x < o) sm[threadIdx.x] += sm[threadIdx.x + o];
        __syncthreads();
    }
    if (threadIdx.x == 0) {
        float avg = sm[0] / (float)NLITS;
        out[0] = logf(avg / (1.0f - avg));
    }
}

// ---------------- host ----------------
#define SYM(var, sym) cudaGetSymbolAddress((void**)&var, sym)

extern "C" void kernel_launch(void* const* d_in, const int* in_sizes, int n_in,
                              void* d_out, int out_size) {
    const float* M      = (const float*)d_in[0];
    const float* L_init = (const float*)d_in[1];
    const float* C_init = (const float*)d_in[2];
    const float* LC_W1 = (const float*)d_in[3];  const float* LC_b1 = (const float*)d_in[4];
    const float* LC_W2 = (const float*)d_in[5];  const float* LC_b2 = (const float*)d_in[6];
    const float* LC_W3 = (const float*)d_in[7];  const float* LC_b3 = (const float*)d_in[8];
    const float* CL_W1 = (const float*)d_in[9];  const float* CL_b1 = (const float*)d_in[10];
    const float* CL_W2 = (const float*)d_in[11]; const float* CL_b2 = (const float*)d_in[12];
    const float* CL_W3 = (const float*)d_in[13]; const float* CL_b3 = (const float*)d_in[14];
    const float* L_Wih = (const float*)d_in[15]; const float* L_Whh = (const float*)d_in[16];
    const float* L_b   = (const float*)d_in[17];
    const float* C_Wih = (const float*)d_in[18]; const float* C_Whh = (const float*)d_in[19];
    const float* C_b   = (const float*)d_in[20];
    const float* V_W1 = (const float*)d_in[21];  const float* V_b1 = (const float*)d_in[22];
    const float* V_W2 = (const float*)d_in[23];  const float* V_b2 = (const float*)d_in[24];
    const float* V_W3 = (const float*)d_in[25];  const float* V_b3 = (const float*)d_in[26];
    float* out = (float*)d_out;

    float *Lh, *Lc, *Ch, *Cc, *b1L, *b1C, *b2L, *b2C, *mlpL, *mlpC, *msgL, *msgC;
    float *gatesC, *gatesL, *partials, *LC3p, *CL3p;
    SYM(Lh, g_Lh); SYM(Lc, g_Lc); SYM(Ch, g_Ch); SYM(Cc, g_Cc);
    SYM(b1L, g_b1L); SYM(b1C, g_b1C); SYM(b2L, g_b2L); SYM(b2C, g_b2C);
    SYM(mlpL, g_mlpL); SYM(mlpC, g_mlpC); SYM(msgL, g_msgL); SYM(msgC, g_msgC);
    SYM(gatesC, g_gatesC); SYM(gatesL, g_gatesL); SYM(partials, g_partials);
    SYM(LC3p, g_LC3p); SYM(CL3p, g_CL3p);

    // adjacency + weight padding + state init
    build_lit_kernel<<<(NLITS + 7) / 8, 256>>>(M);
    build_cls_kernel<<<(NCLS + 7) / 8, 256>>>(M);
    pad_w3_kernel<<<(E * H2P + 255) / 256, 256>>>(LC_W3, LC3p);
    pad_w3_kernel<<<(E * H2P + 255) / 256, 256>>>(CL_W3, CL3p);
    init_states_kernel<<<((NLITS + NCLS) * E + 255) / 256, 256>>>(L_init, C_init);

    GP dummy = {};

    for (int t = 0; t < TSTEPS; t++) {
        // MLP layer 1: lits use LC weights, clauses use CL weights
        GP a1 = {{Lh}, {LC_W1}, LC_b1, b1L, NLITS, 1};
        GP b1 = {{Ch}, {CL_W1}, CL_b1, b1C, NCLS, 1};
        launch_gemm<true>(a1, b1, 2, H1, E, H1);

        // MLP layer 2
        GP a2 = {{b1L}, {LC_W2}, LC_b2, b2L, NLITS, 1};
        GP b2 = {{b1C}, {CL_W2}, CL_b2, b2C, NCLS, 1};
        launch_gemm<true>(a2, b2, 2, H2, H1, H2P);

        // MLP layer 3 (no relu), K padded to 208
        GP a3 = {{b2L}, {LC3p}, LC_b3, mlpL, NLITS, 1};
        GP b3 = {{b2C}, {CL3p}, CL_b3, mlpC, NCLS, 1};
        launch_gemm<false>(a3, b3, 2, E, H2P, E);

        // sparse aggregation (both directions, one launch)
        spmm_both_kernel<<<(NCLS + NLITS + 7) / 8, 256>>>();

        // LSTM gates: msgs@Wih^T + h@Whh^T + b (pre-update h)
        GP ga = {{msgC, Ch}, {C_Wih, C_Whh}, C_b, gatesC, NCLS, 2};
        GP gb = {{msgL, Lh}, {L_Wih, L_Whh}, L_b, gatesL, NLITS, 2};
        launch_gemm<false>(ga, gb, 2, NG, E, NG);

        // pointwise state update
        lstm_pointwise_both<<<((NCLS + NLITS) * E + 255) / 256, 256>>>();
    }

    // final vote MLP + mean + logit
    GP v1 = {{Lh}, {V_W1}, V_b1, b1L, NLITS, 1};
    launch_gemm<true>(v1, dummy, 1, H1, E, H1);
    GP v2 = {{b1L}, {V_W2}, V_b2, b2L, NLITS, 1};
    launch_gemm<true>(v2, dummy, 1, H2, H1, H2P);
    vote_partial_kernel<<<VOTE_BLOCKS, 256>>>(b2L, V_W3, V_b3, partials);
    finalize_kernel<<<1, 512>>>(partials, VOTE_BLOCKS, out);
}